// round 16
// baseline (speedup 1.0000x reference)
#include <cuda_runtime.h>
#include <cuda_fp16.h>
#include <math.h>
#include <cstdint>

#define BATCH 2048
#define SEQ   200
#define HDIM  512
#define MTOT  (BATCH * SEQ)   // 409600
#define NPLANES 4             // 4 o-tiles of 128 cols

// ---------------- static device scratch (no allocation) ----------------
__device__ float  g_l[BATCH * HDIM];          // Wr(last_memory)  [B,512]
__device__ float  g_spart[NPLANES][MTOT];     // partial scores
__device__ __half g_Wh[HDIM * HDIM];          // Ur_w fp16
__device__ __half g_Ah[(size_t)MTOT * HDIM];  // all_memory fp16 (written by score)

// ======================= helpers =======================
__device__ __forceinline__ uint32_t smem_u32(const void* p) {
    uint32_t a;
    asm("{ .reg .u64 t; cvta.to.shared.u64 t, %1; cvt.u32.u64 %0, t; }"
        : "=r"(a) : "l"(p));
    return a;
}
// 64-byte-row swizzle (Swizzle<2,4,3>): conflict-free ldmatrix on 64B rows
#define SWZ64(off) ((off) ^ (((off) >> 3) & 0x30))

#define LDSM_X4(r, a) \
    asm volatile("ldmatrix.sync.aligned.m8n8.x4.shared.b16 {%0,%1,%2,%3}, [%4];" \
        : "=r"((r)[0]), "=r"((r)[1]), "=r"((r)[2]), "=r"((r)[3]) : "r"(a))
#define MMA_F16(d, a, b) \
    asm volatile("mma.sync.aligned.m16n8k16.row.col.f32.f16.f16.f32 " \
        "{%0,%1,%2,%3},{%4,%5,%6,%7},{%8,%9},{%0,%1,%2,%3};" \
        : "+f"((d)[0]), "+f"((d)[1]), "+f"((d)[2]), "+f"((d)[3]) \
        : "r"((a)[0]), "r"((a)[1]), "r"((a)[2]), "r"((a)[3]), \
          "r"((b)[0]), "r"((b)[1]))
#define CPASYNC16(dst, src) \
    asm volatile("cp.async.cg.shared.global [%0], [%1], 16;" \
        :: "r"(dst), "l"(src) : "memory")
#define CPASYNC_COMMIT() asm volatile("cp.async.commit_group;" ::: "memory")
#define CPASYNC_WAITG(n) asm volatile("cp.async.wait_group %0;" :: "n"(n) : "memory")
#define STS128(addr, a, b, c, d) \
    asm volatile("st.shared.v4.b32 [%0], {%1, %2, %3, %4};" \
        :: "r"(addr), "r"(a), "r"(b), "r"(c), "r"(d) : "memory")

__device__ __forceinline__ float fast_tanh(float x) {
    float e = __expf(2.0f * x);
    return 1.0f - __fdividef(2.0f, e + 1.0f);
}

// =============================================================================
// W convert kernel: Ur_w fp32 -> fp16 (tiny, ~5us)
// =============================================================================
__global__ void __launch_bounds__(256)
whalf_kernel(const float* __restrict__ Ur)
{
    int i = blockIdx.x * 256 + threadIdx.x;       // float4 units, 65536
    float4 v = reinterpret_cast<const float4*>(Ur)[i];
    __half2 h0 = __float22half2_rn(make_float2(v.x, v.y));
    __half2 h1 = __float22half2_rn(make_float2(v.z, v.w));
    reinterpret_cast<__half2*>(g_Wh)[2 * i + 0] = h0;
    reinterpret_cast<__half2*>(g_Wh)[2 * i + 1] = h1;
}

// =============================================================================
// K1: l = last_memory @ Wr^T  (SIMT fp32; 32-row tiles -> 256 CTAs, ~30us)
// =============================================================================
__global__ void __launch_bounds__(256)
gemm_l_kernel(const float* __restrict__ A, const float* __restrict__ W)
{
    const int tid = threadIdx.x;
    const int tx  = tid & 15;
    const int ty  = tid >> 4;
    const int m0  = blockIdx.x * 32;
    const int o0  = blockIdx.y * 128;

    __shared__ float As[32][33];
    __shared__ float Ws[128][33];

    float acc[2][8];
#pragma unroll
    for (int i = 0; i < 2; i++)
#pragma unroll
        for (int j = 0; j < 8; j++) acc[i][j] = 0.0f;

    for (int k0 = 0; k0 < HDIM; k0 += 32) {
        {
            int r = tid >> 3, c4 = (tid & 7) << 2;
            float4 v = *reinterpret_cast<const float4*>(&A[(size_t)(m0 + r) * HDIM + k0 + c4]);
            As[r][c4] = v.x; As[r][c4 + 1] = v.y; As[r][c4 + 2] = v.z; As[r][c4 + 3] = v.w;
        }
#pragma unroll
        for (int t = 0; t < 4; t++) {
            int f = t * 256 + tid, r = f >> 3, c4 = (f & 7) << 2;
            float4 v = *reinterpret_cast<const float4*>(&W[(size_t)(o0 + r) * HDIM + k0 + c4]);
            Ws[r][c4] = v.x; Ws[r][c4 + 1] = v.y; Ws[r][c4 + 2] = v.z; Ws[r][c4 + 3] = v.w;
        }
        __syncthreads();
#pragma unroll
        for (int kk = 0; kk < 32; kk++) {
            float a[2], w[8];
#pragma unroll
            for (int i = 0; i < 2; i++) a[i] = As[ty * 2 + i][kk];
#pragma unroll
            for (int j = 0; j < 8; j++) w[j] = Ws[tx + 16 * j][kk];
#pragma unroll
            for (int i = 0; i < 2; i++)
#pragma unroll
                for (int j = 0; j < 8; j++) acc[i][j] += a[i] * w[j];
        }
        __syncthreads();
    }
#pragma unroll
    for (int i = 0; i < 2; i++) {
        int m = m0 + ty * 2 + i;
#pragma unroll
        for (int j = 0; j < 8; j++)
            g_l[(size_t)m * HDIM + o0 + tx + 16 * j] = acc[i][j];
    }
}

// =============================================================================
// K2: fused convert + fp16 HMMA over ALL 4 o-planes, 64 m-rows per CTA.
// 32 iterations x K=64 (two B half-chunks per iter), 5-stage 8KB B ring.
// RACE-FREE split fills:
//   top of iter t:  fill chunk 2t+3 -> stage (2t+3)%5 (occupant 2t-2, read
//                   at iter t-1, protected by this top sync)
//   after MMAs:     fill chunk 2t+4 -> stage (2t+4)%5 (occupant 2t-1, read
//                   at iter t-1; NOT among this iter's read stages 2t%5,
//                   (2t+1)%5)
// Group order: {0}{1}{2} prologue, then {2t+3}(top), {2t+4}(post) -> at top
// of iter t the newest pending group is {2t+2}; WAITG(1) => chunks <= 2t+1.
// smem 113664B x 2 CTAs = 227KB <= 228KB -> occ 2.
// =============================================================================
#define OFF_VRE   0                       // 512 floats
#define OFF_PART  2048                    // 64*4 floats
#define OFF_L     3072                    // 2 x 512 floats
#define OFF_A     7168
#define A_HC      4096                    // 64 rows x 32k fp16
#define OFF_B     (OFF_A + 16 * A_HC)     // 72704
#define B_STG     8192
#define SMEM_TOTAL (OFF_B + 5 * B_STG)    // 113664

__global__ void __launch_bounds__(256, 2)
score_kernel(const float* __restrict__ A,       // all_memory fp32 [M,512]
             const float* __restrict__ vre)     // [512]
{
    extern __shared__ char smem[];
    const uint32_t sb  = smem_u32(smem);
    const int tid = threadIdx.x;
    const int wid = tid >> 5;
    const int lid = tid & 31;
    const int wm  = wid >> 2;     // 0..1
    const int wn  = wid & 3;      // 0..3
    const int m0  = blockIdx.x * 64;
    const int b0  = m0 / SEQ;
    const int b1  = (m0 + 63) / SEQ;

    float* svre  = reinterpret_cast<float*>(smem + OFF_VRE);
    float* smemL = reinterpret_cast<float*>(smem + OFF_L);
    svre[tid] = vre[tid];
    svre[tid + 256] = vre[tid + 256];
    smemL[tid]       = g_l[(size_t)b0 * HDIM + tid];
    smemL[tid + 256] = g_l[(size_t)b0 * HDIM + tid + 256];
    smemL[tid + 512] = g_l[(size_t)b1 * HDIM + tid];
    smemL[tid + 768] = g_l[(size_t)b1 * HDIM + tid + 256];

    // A producer: thread -> (row ar, 8-float quarter aq)
    const int ar = tid >> 2;                  // 0..63
    const int aq = tid & 3;                   // 0..3
    const float* Abase = A    + (size_t)(m0 + ar) * HDIM + aq * 8;
    __half*      AhOut = g_Ah + (size_t)(m0 + ar) * HDIM + aq * 8;
    const uint32_t aoff = (uint32_t)(ar * 64 + aq * 16);

    // B producer: thread -> (row br, half bh); 2 x cp.async 16B per chunk
    const int br = tid >> 1;                  // 0..127
    const int bh = tid & 1;
    const uint32_t boff = (uint32_t)(br * 64 + bh * 32);

    // B consumer X4-pairing addresses (validated lane mapping)
    const uint32_t b_row_lo = wn * 32 + ((lid >> 4) & 1) * 8 + (lid & 7);
    const uint32_t b_k_off  = ((lid >> 3) & 1) * 16;

    float acc[2][4][4];
#pragma unroll
    for (int i = 0; i < 2; i++)
#pragma unroll
        for (int j = 0; j < 4; j++)
#pragma unroll
            for (int q = 0; q < 4; q++) acc[i][j][q] = 0.0f;

    // ---- prologue: B chunks 0,1,2 (three groups); A hk 0,1; va for 2,3 ----
#pragma unroll
    for (int bi = 0; bi < 3; bi++) {
        const __half* src = g_Wh + (size_t)br * HDIM + bi * 32 + bh * 16;
        const uint32_t st = sb + OFF_B + bi * B_STG;
        CPASYNC16(st + SWZ64(boff),      src);
        CPASYNC16(st + SWZ64(boff + 16), src + 8);
        CPASYNC_COMMIT();
    }
    float4 va0, va1, va2, va3;
#pragma unroll
    for (int hk = 0; hk < 2; hk++) {
        float4 u = *reinterpret_cast<const float4*>(Abase + hk * 32);
        float4 v = *reinterpret_cast<const float4*>(Abase + hk * 32 + 4);
        __half2 h0 = __float22half2_rn(make_float2(u.x, u.y));
        __half2 h1 = __float22half2_rn(make_float2(u.z, u.w));
        __half2 h2 = __float22half2_rn(make_float2(v.x, v.y));
        __half2 h3 = __float22half2_rn(make_float2(v.z, v.w));
        STS128(sb + OFF_A + hk * A_HC + SWZ64(aoff),
               reinterpret_cast<uint32_t&>(h0), reinterpret_cast<uint32_t&>(h1),
               reinterpret_cast<uint32_t&>(h2), reinterpret_cast<uint32_t&>(h3));
        uint4 o;
        o.x = reinterpret_cast<uint32_t&>(h0); o.y = reinterpret_cast<uint32_t&>(h1);
        o.z = reinterpret_cast<uint32_t&>(h2); o.w = reinterpret_cast<uint32_t&>(h3);
        *reinterpret_cast<uint4*>(AhOut + hk * 32) = o;
    }
    va0 = *reinterpret_cast<const float4*>(Abase + 64);
    va1 = *reinterpret_cast<const float4*>(Abase + 68);
    va2 = *reinterpret_cast<const float4*>(Abase + 96);
    va3 = *reinterpret_cast<const float4*>(Abase + 100);

#pragma unroll 1
    for (int t = 0; t < 32; ++t) {
        const int pl = t >> 3;                 // plane 0..3

        if (t < 31) { CPASYNC_WAITG(1); } else { CPASYNC_WAITG(0); }
        __syncthreads();

        // ---- top fill: chunk 2t+3 (stage occupant read at iter t-1) ----
        if (2 * t + 3 < 64) {
            const int bi = 2 * t + 3;
            const __half* src = g_Wh + (size_t)((bi >> 4) * 128 + br) * HDIM
                              + (bi & 15) * 32 + bh * 16;
            const uint32_t stn = sb + OFF_B + (bi % 5) * B_STG;
            CPASYNC16(stn + SWZ64(boff),      src);
            CPASYNC16(stn + SWZ64(boff + 16), src + 8);
            CPASYNC_COMMIT();
        }

        // plane 0: convert A hk 2t+2, 2t+3 (used next iter); prefetch next va
        if (pl == 0 && t < 7) {
            {
                __half2 h0 = __float22half2_rn(make_float2(va0.x, va0.y));
                __half2 h1 = __float22half2_rn(make_float2(va0.z, va0.w));
                __half2 h2 = __float22half2_rn(make_float2(va1.x, va1.y));
                __half2 h3 = __float22half2_rn(make_float2(va1.z, va1.w));
                STS128(sb + OFF_A + (2 * t + 2) * A_HC + SWZ64(aoff),
                       reinterpret_cast<uint32_t&>(h0), reinterpret_cast<uint32_t&>(h1),
                       reinterpret_cast<uint32_t&>(h2), reinterpret_cast<uint32_t&>(h3));
                uint4 o;
                o.x = reinterpret_cast<uint32_t&>(h0); o.y = reinterpret_cast<uint32_t&>(h1);
                o.z = reinterpret_cast<uint32_t&>(h2); o.w = reinterpret_cast<uint32_t&>(h3);
                *reinterpret_cast<uint4*>(AhOut + (2 * t + 2) * 32) = o;
            }
            {
                __half2 h0 = __float22half2_rn(make_float2(va2.x, va2.y));
                __half2 h1 = __float22half2_rn(make_float2(va2.z, va2.w));
                __half2 h2 = __float22half2_rn(make_float2(va3.x, va3.y));
                __half2 h3 = __float22half2_rn(make_float2(va3.z, va3.w));
                STS128(sb + OFF_A + (2 * t + 3) * A_HC + SWZ64(aoff),
                       reinterpret_cast<uint32_t&>(h0), reinterpret_cast<uint32_t&>(h1),
                       reinterpret_cast<uint32_t&>(h2), reinterpret_cast<uint32_t&>(h3));
                uint4 o;
                o.x = reinterpret_cast<uint32_t&>(h0); o.y = reinterpret_cast<uint32_t&>(h1);
                o.z = reinterpret_cast<uint32_t&>(h2); o.w = reinterpret_cast<uint32_t&>(h3);
                *reinterpret_cast<uint4*>(AhOut + (2 * t + 3) * 32) = o;
            }
            if (t < 6) {
                va0 = *reinterpret_cast<const float4*>(Abase + (2 * t + 4) * 32);
                va1 = *reinterpret_cast<const float4*>(Abase + (2 * t + 4) * 32 + 4);
                va2 = *reinterpret_cast<const float4*>(Abase + (2 * t + 5) * 32);
                va3 = *reinterpret_cast<const float4*>(Abase + (2 * t + 5) * 32 + 4);
            }
        }

        // ---- MMAs: chunks 2t, 2t+1 (K=64 total) ----
#pragma unroll
        for (int d = 0; d < 2; d++) {
            const int hc = 2 * t + d;
            const uint32_t stA = sb + OFF_A + (hc & 15) * A_HC;
            const uint32_t stB = sb + OFF_B + (hc % 5) * B_STG;
#pragma unroll
            for (int ks = 0; ks < 2; ks++) {
                uint32_t bf[4][2];
#pragma unroll
                for (int pr = 0; pr < 2; pr++) {
                    uint32_t t4[4];
                    uint32_t row = b_row_lo + pr * 16;
                    LDSM_X4(t4, stB + SWZ64(row * 64 + ks * 32 + b_k_off));
                    bf[pr * 2 + 0][0] = t4[0]; bf[pr * 2 + 0][1] = t4[1];
                    bf[pr * 2 + 1][0] = t4[2]; bf[pr * 2 + 1][1] = t4[3];
                }
#pragma unroll
                for (int mf = 0; mf < 2; mf++) {
                    uint32_t row = wm * 32 + mf * 16 + (lid & 15);
                    uint32_t kb  = ks * 32 + (lid >> 4) * 16;
                    uint32_t af[4];
                    LDSM_X4(af, stA + SWZ64(row * 64 + kb));
#pragma unroll
                    for (int nf = 0; nf < 4; nf++)
                        MMA_F16(acc[mf][nf], af, bf[nf]);
                }
            }
        }

        // ---- post fill: chunk 2t+4 (stage occupant 2t-1, read iter t-1) ----
        if (2 * t + 4 < 64) {
            const int bi = 2 * t + 4;
            const __half* src = g_Wh + (size_t)((bi >> 4) * 128 + br) * HDIM
                              + (bi & 15) * 32 + bh * 16;
            const uint32_t stn = sb + OFF_B + (bi % 5) * B_STG;
            CPASYNC16(stn + SWZ64(boff),      src);
            CPASYNC16(stn + SWZ64(boff + 16), src + 8);
            CPASYNC_COMMIT();
        }

        // ---- end of plane: fused epilogue, reset acc ----
        if ((t & 7) == 7) {
            float* part = reinterpret_cast<float*>(smem + OFF_PART);
            const int o0 = pl * 128;
            const int r0 = lid >> 2;
            const int cb = 2 * (lid & 3);
#pragma unroll
            for (int mf = 0; mf < 2; mf++) {
                int R0 = wm * 32 + mf * 16 + r0;
                int R1 = R0 + 8;
                const float* lA = smemL + (((m0 + R0) / SEQ) == b0 ? 0 : 512) + o0;
                const float* lB = smemL + (((m0 + R1) / SEQ) == b0 ? 0 : 512) + o0;
                float p0 = 0.0f, p1 = 0.0f;
#pragma unroll
                for (int nf = 0; nf < 4; nf++) {
                    int cl = wn * 32 + nf * 8 + cb;
                    p0 += fast_tanh(acc[mf][nf][0] + lA[cl])     * svre[o0 + cl];
                    p0 += fast_tanh(acc[mf][nf][1] + lA[cl + 1]) * svre[o0 + cl + 1];
                    p1 += fast_tanh(acc[mf][nf][2] + lB[cl])     * svre[o0 + cl];
                    p1 += fast_tanh(acc[mf][nf][3] + lB[cl + 1]) * svre[o0 + cl + 1];
#pragma unroll
                    for (int q = 0; q < 4; q++) acc[mf][nf][q] = 0.0f;
                }
                p0 += __shfl_xor_sync(0xffffffffu, p0, 1);
                p0 += __shfl_xor_sync(0xffffffffu, p0, 2);
                p1 += __shfl_xor_sync(0xffffffffu, p1, 1);
                p1 += __shfl_xor_sync(0xffffffffu, p1, 2);
                if ((lid & 3) == 0) {
                    part[R0 * 4 + wn] = p0;
                    part[R1 * 4 + wn] = p1;
                }
            }
            __syncthreads();
            if (tid < 64) {
                float s = part[tid * 4 + 0] + part[tid * 4 + 1]
                        + part[tid * 4 + 2] + part[tid * 4 + 3];
                g_spart[pl][m0 + tid] = s;
            }
        }
    }
}

// =============================================================================
// K3: per-batch softmax over S, context (fp16 g_Ah, 4-way ILP), 2-class head
// =============================================================================
__device__ __forceinline__ float block_reduce_max(float v, float* red, int tid) {
    red[tid] = v; __syncthreads();
#pragma unroll
    for (int off = 128; off > 0; off >>= 1) {
        if (tid < off) red[tid] = fmaxf(red[tid], red[tid + off]);
        __syncthreads();
    }
    float r = red[0]; __syncthreads(); return r;
}
__device__ __forceinline__ float block_reduce_sum(float v, float* red, int tid) {
    red[tid] = v; __syncthreads();
#pragma unroll
    for (int off = 128; off > 0; off >>= 1) {
        if (tid < off) red[tid] = red[tid] + red[tid + off];
        __syncthreads();
    }
    float r = red[0]; __syncthreads(); return r;
}

__global__ void __launch_bounds__(256)
finish_kernel(const float* __restrict__ wre,
              float* __restrict__ out)
{
    const int b = blockIdx.x, tid = threadIdx.x;
    __shared__ float attn[SEQ];
    __shared__ float red[256];

    float sc = -INFINITY;
    if (tid < SEQ) {
        float s = 0.0f;
#pragma unroll
        for (int p = 0; p < NPLANES; p++) s += g_spart[p][(size_t)b * SEQ + tid];
        sc = s;
    }
    float mx = block_reduce_max(sc, red, tid);
    float e = (tid < SEQ) ? expf(sc - mx) : 0.0f;
    float denom = block_reduce_sum(e, red, tid);
    if (tid < SEQ) attn[tid] = e / denom;
    __syncthreads();

    // ctx from fp16 A: 4 independent accumulator pairs (proven 80us config)
    const __half* am = g_Ah + (size_t)b * SEQ * HDIM;
    float c0a = 0.0f, c1a = 0.0f, c0b = 0.0f, c1b = 0.0f;
    float c0c = 0.0f, c1c = 0.0f, c0d = 0.0f, c1d = 0.0f;
#pragma unroll 1
    for (int s = 0; s < SEQ; s += 4) {
        float w0 = attn[s],     w1 = attn[s + 1];
        float w2 = attn[s + 2], w3 = attn[s + 3];
        __half2 ha = *reinterpret_cast<const __half2*>(am + (size_t)s * HDIM + 2 * tid);
        __half2 hb = *reinterpret_cast<const __half2*>(am + (size_t)(s + 1) * HDIM + 2 * tid);
        __half2 hc = *reinterpret_cast<const __half2*>(am + (size_t)(s + 2) * HDIM + 2 * tid);
        __half2 hd = *reinterpret_cast<const __half2*>(am + (size_t)(s + 3) * HDIM + 2 * tid);
        float2 fa = __half22float2(ha);
        float2 fb = __half22float2(hb);
        float2 fc = __half22float2(hc);
        float2 fd = __half22float2(hd);
        c0a = fmaf(w0, fa.x, c0a); c1a = fmaf(w0, fa.y, c1a);
        c0b = fmaf(w1, fb.x, c0b); c1b = fmaf(w1, fb.y, c1b);
        c0c = fmaf(w2, fc.x, c0c); c1c = fmaf(w2, fc.y, c1c);
        c0d = fmaf(w3, fd.x, c0d); c1d = fmaf(w3, fd.y, c1d);
    }
    float c0 = (c0a + c0b) + (c0c + c0d);
    float c1 = (c1a + c1b) + (c1c + c1d);
    float p0 = c0 * wre[2 * tid]        + c1 * wre[2 * tid + 1];
    float p1 = c0 * wre[HDIM + 2 * tid] + c1 * wre[HDIM + 2 * tid + 1];
    float L0 = block_reduce_sum(p0, red, tid);
    float L1 = block_reduce_sum(p1, red, tid);
    if (tid == 0) {
        float m  = fmaxf(L0, L1);
        float e0 = expf(L0 - m), e1 = expf(L1 - m);
        float inv = 1.0f / (e0 + e1);
        out[(size_t)b * 2 + 0] = e0 * inv;
        out[(size_t)b * 2 + 1] = e1 * inv;
    }
}

// =============================================================================
// launch
// =============================================================================
extern "C" void kernel_launch(void* const* d_in, const int* in_sizes, int n_in,
                              void* d_out, int out_size)
{
    const float* all_memory  = (const float*)d_in[0];
    const float* last_memory = (const float*)d_in[1];
    const float* Ur_w        = (const float*)d_in[2];
    const float* Wr_w        = (const float*)d_in[3];
    const float* Vre_w       = (const float*)d_in[4];
    const float* Wre_w       = (const float*)d_in[5];
    float* out = (float*)d_out;

    cudaFuncSetAttribute(score_kernel,
                         cudaFuncAttributeMaxDynamicSharedMemorySize, SMEM_TOTAL);

    whalf_kernel<<<256, 256>>>(Ur_w);
    gemm_l_kernel<<<dim3(BATCH / 32, HDIM / 128), 256>>>(last_memory, Wr_w);
    score_kernel<<<MTOT / 64, 256, SMEM_TOTAL>>>(all_memory, Vre_w);
    finish_kernel<<<BATCH, 256>>>(Wre_w, out);
}

// round 17
// speedup vs baseline: 1.0148x; 1.0148x over previous
#include <cuda_runtime.h>
#include <cuda_fp16.h>
#include <math.h>
#include <cstdint>

#define BATCH 2048
#define SEQ   200
#define HDIM  512
#define MTOT  (BATCH * SEQ)   // 409600
#define NPLANES 4             // 4 o-tiles of 128 cols

// ---------------- static device scratch (no allocation) ----------------
__device__ float  g_l[BATCH * HDIM];          // Wr(last_memory)  [B,512]
__device__ float  g_spart[NPLANES][MTOT];     // partial scores
__device__ __half g_Wh[HDIM * HDIM];          // Ur_w fp16
__device__ __half g_Ah[(size_t)MTOT * HDIM];  // all_memory fp16 (written by score)

// ======================= helpers =======================
__device__ __forceinline__ uint32_t smem_u32(const void* p) {
    uint32_t a;
    asm("{ .reg .u64 t; cvta.to.shared.u64 t, %1; cvt.u32.u64 %0, t; }"
        : "=r"(a) : "l"(p));
    return a;
}
// 64-byte-row swizzle (Swizzle<2,4,3>): conflict-free ldmatrix on 64B rows
#define SWZ64(off) ((off) ^ (((off) >> 3) & 0x30))

#define LDSM_X4(r, a) \
    asm volatile("ldmatrix.sync.aligned.m8n8.x4.shared.b16 {%0,%1,%2,%3}, [%4];" \
        : "=r"((r)[0]), "=r"((r)[1]), "=r"((r)[2]), "=r"((r)[3]) : "r"(a))
#define MMA_F16(d, a, b) \
    asm volatile("mma.sync.aligned.m16n8k16.row.col.f32.f16.f16.f32 " \
        "{%0,%1,%2,%3},{%4,%5,%6,%7},{%8,%9},{%0,%1,%2,%3};" \
        : "+f"((d)[0]), "+f"((d)[1]), "+f"((d)[2]), "+f"((d)[3]) \
        : "r"((a)[0]), "r"((a)[1]), "r"((a)[2]), "r"((a)[3]), \
          "r"((b)[0]), "r"((b)[1]))
#define CPASYNC16(dst, src) \
    asm volatile("cp.async.cg.shared.global [%0], [%1], 16;" \
        :: "r"(dst), "l"(src) : "memory")
#define CPASYNC_COMMIT() asm volatile("cp.async.commit_group;" ::: "memory")
#define CPASYNC_WAITG(n) asm volatile("cp.async.wait_group %0;" :: "n"(n) : "memory")
#define STS128(addr, a, b, c, d) \
    asm volatile("st.shared.v4.b32 [%0], {%1, %2, %3, %4};" \
        :: "r"(addr), "r"(a), "r"(b), "r"(c), "r"(d) : "memory")

__device__ __forceinline__ float fast_tanh(float x) {
    float e = __expf(2.0f * x);
    return 1.0f - __fdividef(2.0f, e + 1.0f);
}

// =============================================================================
// W convert kernel: Ur_w fp32 -> fp16 (tiny, ~5us)
// =============================================================================
__global__ void __launch_bounds__(256)
whalf_kernel(const float* __restrict__ Ur)
{
    int i = blockIdx.x * 256 + threadIdx.x;       // float4 units, 65536
    float4 v = reinterpret_cast<const float4*>(Ur)[i];
    __half2 h0 = __float22half2_rn(make_float2(v.x, v.y));
    __half2 h1 = __float22half2_rn(make_float2(v.z, v.w));
    reinterpret_cast<__half2*>(g_Wh)[2 * i + 0] = h0;
    reinterpret_cast<__half2*>(g_Wh)[2 * i + 1] = h1;
}

// =============================================================================
// K1: l = last_memory @ Wr^T  (SIMT fp32; 32-row tiles -> 256 CTAs, ~30us)
// =============================================================================
__global__ void __launch_bounds__(256)
gemm_l_kernel(const float* __restrict__ A, const float* __restrict__ W)
{
    const int tid = threadIdx.x;
    const int tx  = tid & 15;
    const int ty  = tid >> 4;
    const int m0  = blockIdx.x * 32;
    const int o0  = blockIdx.y * 128;

    __shared__ float As[32][33];
    __shared__ float Ws[128][33];

    float acc[2][8];
#pragma unroll
    for (int i = 0; i < 2; i++)
#pragma unroll
        for (int j = 0; j < 8; j++) acc[i][j] = 0.0f;

    for (int k0 = 0; k0 < HDIM; k0 += 32) {
        {
            int r = tid >> 3, c4 = (tid & 7) << 2;
            float4 v = *reinterpret_cast<const float4*>(&A[(size_t)(m0 + r) * HDIM + k0 + c4]);
            As[r][c4] = v.x; As[r][c4 + 1] = v.y; As[r][c4 + 2] = v.z; As[r][c4 + 3] = v.w;
        }
#pragma unroll
        for (int t = 0; t < 4; t++) {
            int f = t * 256 + tid, r = f >> 3, c4 = (f & 7) << 2;
            float4 v = *reinterpret_cast<const float4*>(&W[(size_t)(o0 + r) * HDIM + k0 + c4]);
            Ws[r][c4] = v.x; Ws[r][c4 + 1] = v.y; Ws[r][c4 + 2] = v.z; Ws[r][c4 + 3] = v.w;
        }
        __syncthreads();
#pragma unroll
        for (int kk = 0; kk < 32; kk++) {
            float a[2], w[8];
#pragma unroll
            for (int i = 0; i < 2; i++) a[i] = As[ty * 2 + i][kk];
#pragma unroll
            for (int j = 0; j < 8; j++) w[j] = Ws[tx + 16 * j][kk];
#pragma unroll
            for (int i = 0; i < 2; i++)
#pragma unroll
                for (int j = 0; j < 8; j++) acc[i][j] += a[i] * w[j];
        }
        __syncthreads();
    }
#pragma unroll
    for (int i = 0; i < 2; i++) {
        int m = m0 + ty * 2 + i;
#pragma unroll
        for (int j = 0; j < 8; j++)
            g_l[(size_t)m * HDIM + o0 + tx + 16 * j] = acc[i][j];
    }
}

// =============================================================================
// K2: fused convert + fp16 HMMA over ALL 4 o-planes, 64 m-rows per CTA.
// R15 score kernel verbatim (measured best ~835us): 64 iters x K=32,
// 3-stage 8KB B ring, fill AFTER MMAs, X4-paired B fragments, smem g_l.
// smem ~95KB -> 2 CTAs/SM.
// =============================================================================
#define OFF_VRE   0                       // 512 floats
#define OFF_PART  2048                    // 64*4 floats
#define OFF_L     3072                    // 2 x 512 floats
#define OFF_A     7168
#define A_HC      4096                    // 64 rows x 32k fp16
#define OFF_B     (OFF_A + 16 * A_HC)     // 72704
#define B_STG     8192
#define SMEM_TOTAL (OFF_B + 3 * B_STG)    // 97280

__global__ void __launch_bounds__(256, 2)
score_kernel(const float* __restrict__ A,       // all_memory fp32 [M,512]
             const float* __restrict__ vre)     // [512]
{
    extern __shared__ char smem[];
    const uint32_t sb  = smem_u32(smem);
    const int tid = threadIdx.x;
    const int wid = tid >> 5;
    const int lid = tid & 31;
    const int wm  = wid >> 2;     // 0..1
    const int wn  = wid & 3;      // 0..3
    const int m0  = blockIdx.x * 64;
    const int b0  = m0 / SEQ;
    const int b1  = (m0 + 63) / SEQ;

    float* svre  = reinterpret_cast<float*>(smem + OFF_VRE);
    float* smemL = reinterpret_cast<float*>(smem + OFF_L);
    svre[tid] = vre[tid];
    svre[tid + 256] = vre[tid + 256];
    smemL[tid]       = g_l[(size_t)b0 * HDIM + tid];
    smemL[tid + 256] = g_l[(size_t)b0 * HDIM + tid + 256];
    smemL[tid + 512] = g_l[(size_t)b1 * HDIM + tid];
    smemL[tid + 768] = g_l[(size_t)b1 * HDIM + tid + 256];

    // A producer: thread -> (row ar, 8-float quarter aq)
    const int ar = tid >> 2;                  // 0..63
    const int aq = tid & 3;                   // 0..3
    const float* Abase = A    + (size_t)(m0 + ar) * HDIM + aq * 8;
    __half*      AhOut = g_Ah + (size_t)(m0 + ar) * HDIM + aq * 8;
    const uint32_t aoff = (uint32_t)(ar * 64 + aq * 16);

    // B producer: thread -> (row br, half bh); 2 x cp.async 16B / chunk
    const int br = tid >> 1;                  // 0..127
    const int bh = tid & 1;
    const uint32_t boff = (uint32_t)(br * 64 + bh * 32);

    // B consumer X4-pairing addresses
    const uint32_t b_row_lo = wn * 32 + ((lid >> 4) & 1) * 8 + (lid & 7);
    const uint32_t b_k_off  = ((lid >> 3) & 1) * 16;

    float acc[2][4][4];
#pragma unroll
    for (int i = 0; i < 2; i++)
#pragma unroll
        for (int j = 0; j < 4; j++)
#pragma unroll
            for (int q = 0; q < 4; q++) acc[i][j][q] = 0.0f;

    // ---- prologue: B half-chunks 0,1 into stages 0,1 (two groups) ----
#pragma unroll
    for (int p = 0; p < 2; p++) {
        const __half* src = g_Wh + (size_t)br * HDIM + p * 32 + bh * 16;
        const uint32_t st = sb + OFF_B + p * B_STG;
        CPASYNC16(st + SWZ64(boff),      src);
        CPASYNC16(st + SWZ64(boff + 16), src + 8);
        CPASYNC_COMMIT();
    }
    // A: convert half-chunk 0, prefetch half-chunk 1
    float4 va0, va1;
    va0 = *reinterpret_cast<const float4*>(Abase);
    va1 = *reinterpret_cast<const float4*>(Abase + 4);
    {
        __half2 h0 = __float22half2_rn(make_float2(va0.x, va0.y));
        __half2 h1 = __float22half2_rn(make_float2(va0.z, va0.w));
        __half2 h2 = __float22half2_rn(make_float2(va1.x, va1.y));
        __half2 h3 = __float22half2_rn(make_float2(va1.z, va1.w));
        STS128(sb + OFF_A + SWZ64(aoff),
               reinterpret_cast<uint32_t&>(h0), reinterpret_cast<uint32_t&>(h1),
               reinterpret_cast<uint32_t&>(h2), reinterpret_cast<uint32_t&>(h3));
        uint4 o;
        o.x = reinterpret_cast<uint32_t&>(h0); o.y = reinterpret_cast<uint32_t&>(h1);
        o.z = reinterpret_cast<uint32_t&>(h2); o.w = reinterpret_cast<uint32_t&>(h3);
        *reinterpret_cast<uint4*>(AhOut) = o;
    }
    va0 = *reinterpret_cast<const float4*>(Abase + 32);
    va1 = *reinterpret_cast<const float4*>(Abase + 36);

#pragma unroll 1
    for (int t = 0; t < 64; ++t) {
        const int pl = t >> 4, c = t & 15;

        if (t < 63) { CPASYNC_WAITG(1); } else { CPASYNC_WAITG(0); }
        __syncthreads();

        // plane 0: convert A half-chunk c+1 (used next iteration), prefetch c+2
        if (pl == 0 && c < 15) {
            __half2 h0 = __float22half2_rn(make_float2(va0.x, va0.y));
            __half2 h1 = __float22half2_rn(make_float2(va0.z, va0.w));
            __half2 h2 = __float22half2_rn(make_float2(va1.x, va1.y));
            __half2 h3 = __float22half2_rn(make_float2(va1.z, va1.w));
            STS128(sb + OFF_A + (c + 1) * A_HC + SWZ64(aoff),
                   reinterpret_cast<uint32_t&>(h0), reinterpret_cast<uint32_t&>(h1),
                   reinterpret_cast<uint32_t&>(h2), reinterpret_cast<uint32_t&>(h3));
            uint4 o;
            o.x = reinterpret_cast<uint32_t&>(h0); o.y = reinterpret_cast<uint32_t&>(h1);
            o.z = reinterpret_cast<uint32_t&>(h2); o.w = reinterpret_cast<uint32_t&>(h3);
            *reinterpret_cast<uint4*>(AhOut + (c + 1) * 32) = o;
            if (c < 14) {
                va0 = *reinterpret_cast<const float4*>(Abase + (c + 2) * 32);
                va1 = *reinterpret_cast<const float4*>(Abase + (c + 2) * 32 + 4);
            }
        }

        // ---- MMAs: A half-chunk c (smem) x B stage t%3 ----
        const uint32_t stA = sb + OFF_A + c * A_HC;
        const uint32_t stB = sb + OFF_B + (t % 3) * B_STG;
#pragma unroll
        for (int ks = 0; ks < 2; ks++) {
            uint32_t bf[4][2];
#pragma unroll
            for (int pr = 0; pr < 2; pr++) {
                uint32_t t4[4];
                uint32_t row = b_row_lo + pr * 16;
                LDSM_X4(t4, stB + SWZ64(row * 64 + ks * 32 + b_k_off));
                bf[pr * 2 + 0][0] = t4[0]; bf[pr * 2 + 0][1] = t4[1];
                bf[pr * 2 + 1][0] = t4[2]; bf[pr * 2 + 1][1] = t4[3];
            }
#pragma unroll
            for (int mf = 0; mf < 2; mf++) {
                uint32_t row = wm * 32 + mf * 16 + (lid & 15);
                uint32_t kb  = ks * 32 + (lid >> 4) * 16;
                uint32_t af[4];
                LDSM_X4(af, stA + SWZ64(row * 64 + kb));
#pragma unroll
                for (int nf = 0; nf < 4; nf++)
                    MMA_F16(acc[mf][nf], af, bf[nf]);
            }
        }

        // ---- fill B half-chunk t+2 into stage (t+2)%3 (AFTER the MMAs) ----
        if (t + 2 < 64) {
            const int bi = t + 2;
            const __half* src = g_Wh + (size_t)((bi >> 4) * 128 + br) * HDIM
                              + (bi & 15) * 32 + bh * 16;
            const uint32_t stn = sb + OFF_B + ((t + 2) % 3) * B_STG;
            CPASYNC16(stn + SWZ64(boff),      src);
            CPASYNC16(stn + SWZ64(boff + 16), src + 8);
            CPASYNC_COMMIT();
        }

        // ---- end of plane: fused epilogue, reset acc ----
        if (c == 15) {
            float* part = reinterpret_cast<float*>(smem + OFF_PART);
            const int o0 = pl * 128;
            const int r0 = lid >> 2;
            const int cb = 2 * (lid & 3);
#pragma unroll
            for (int mf = 0; mf < 2; mf++) {
                int R0 = wm * 32 + mf * 16 + r0;
                int R1 = R0 + 8;
                const float* lA = smemL + (((m0 + R0) / SEQ) == b0 ? 0 : 512) + o0;
                const float* lB = smemL + (((m0 + R1) / SEQ) == b0 ? 0 : 512) + o0;
                float p0 = 0.0f, p1 = 0.0f;
#pragma unroll
                for (int nf = 0; nf < 4; nf++) {
                    int cl = wn * 32 + nf * 8 + cb;
                    p0 += fast_tanh(acc[mf][nf][0] + lA[cl])     * svre[o0 + cl];
                    p0 += fast_tanh(acc[mf][nf][1] + lA[cl + 1]) * svre[o0 + cl + 1];
                    p1 += fast_tanh(acc[mf][nf][2] + lB[cl])     * svre[o0 + cl];
                    p1 += fast_tanh(acc[mf][nf][3] + lB[cl + 1]) * svre[o0 + cl + 1];
#pragma unroll
                    for (int q = 0; q < 4; q++) acc[mf][nf][q] = 0.0f;
                }
                p0 += __shfl_xor_sync(0xffffffffu, p0, 1);
                p0 += __shfl_xor_sync(0xffffffffu, p0, 2);
                p1 += __shfl_xor_sync(0xffffffffu, p1, 1);
                p1 += __shfl_xor_sync(0xffffffffu, p1, 2);
                if ((lid & 3) == 0) {
                    part[R0 * 4 + wn] = p0;
                    part[R1 * 4 + wn] = p1;
                }
            }
            __syncthreads();
            if (tid < 64) {
                float s = part[tid * 4 + 0] + part[tid * 4 + 1]
                        + part[tid * 4 + 2] + part[tid * 4 + 3];
                g_spart[pl][m0 + tid] = s;
            }
        }
    }
}

// =============================================================================
// K3: per-batch softmax over S, context (fp16 g_Ah, 4-way ILP), 2-class head
// (R14/R16 proven 80us configuration: regs 32, occ ~87%)
// =============================================================================
__device__ __forceinline__ float block_reduce_max(float v, float* red, int tid) {
    red[tid] = v; __syncthreads();
#pragma unroll
    for (int off = 128; off > 0; off >>= 1) {
        if (tid < off) red[tid] = fmaxf(red[tid], red[tid + off]);
        __syncthreads();
    }
    float r = red[0]; __syncthreads(); return r;
}
__device__ __forceinline__ float block_reduce_sum(float v, float* red, int tid) {
    red[tid] = v; __syncthreads();
#pragma unroll
    for (int off = 128; off > 0; off >>= 1) {
        if (tid < off) red[tid] = red[tid] + red[tid + off];
        __syncthreads();
    }
    float r = red[0]; __syncthreads(); return r;
}

__global__ void __launch_bounds__(256)
finish_kernel(const float* __restrict__ wre,
              float* __restrict__ out)
{
    const int b = blockIdx.x, tid = threadIdx.x;
    __shared__ float attn[SEQ];
    __shared__ float red[256];

    float sc = -INFINITY;
    if (tid < SEQ) {
        float s = 0.0f;
#pragma unroll
        for (int p = 0; p < NPLANES; p++) s += g_spart[p][(size_t)b * SEQ + tid];
        sc = s;
    }
    float mx = block_reduce_max(sc, red, tid);
    float e = (tid < SEQ) ? expf(sc - mx) : 0.0f;
    float denom = block_reduce_sum(e, red, tid);
    if (tid < SEQ) attn[tid] = e / denom;
    __syncthreads();

    const __half* am = g_Ah + (size_t)b * SEQ * HDIM;
    float c0a = 0.0f, c1a = 0.0f, c0b = 0.0f, c1b = 0.0f;
    float c0c = 0.0f, c1c = 0.0f, c0d = 0.0f, c1d = 0.0f;
#pragma unroll 1
    for (int s = 0; s < SEQ; s += 4) {
        float w0 = attn[s],     w1 = attn[s + 1];
        float w2 = attn[s + 2], w3 = attn[s + 3];
        __half2 ha = *reinterpret_cast<const __half2*>(am + (size_t)s * HDIM + 2 * tid);
        __half2 hb = *reinterpret_cast<const __half2*>(am + (size_t)(s + 1) * HDIM + 2 * tid);
        __half2 hc = *reinterpret_cast<const __half2*>(am + (size_t)(s + 2) * HDIM + 2 * tid);
        __half2 hd = *reinterpret_cast<const __half2*>(am + (size_t)(s + 3) * HDIM + 2 * tid);
        float2 fa = __half22float2(ha);
        float2 fb = __half22float2(hb);
        float2 fc = __half22float2(hc);
        float2 fd = __half22float2(hd);
        c0a = fmaf(w0, fa.x, c0a); c1a = fmaf(w0, fa.y, c1a);
        c0b = fmaf(w1, fb.x, c0b); c1b = fmaf(w1, fb.y, c1b);
        c0c = fmaf(w2, fc.x, c0c); c1c = fmaf(w2, fc.y, c1c);
        c0d = fmaf(w3, fd.x, c0d); c1d = fmaf(w3, fd.y, c1d);
    }
    float c0 = (c0a + c0b) + (c0c + c0d);
    float c1 = (c1a + c1b) + (c1c + c1d);
    float p0 = c0 * wre[2 * tid]        + c1 * wre[2 * tid + 1];
    float p1 = c0 * wre[HDIM + 2 * tid] + c1 * wre[HDIM + 2 * tid + 1];
    float L0 = block_reduce_sum(p0, red, tid);
    float L1 = block_reduce_sum(p1, red, tid);
    if (tid == 0) {
        float m  = fmaxf(L0, L1);
        float e0 = expf(L0 - m), e1 = expf(L1 - m);
        float inv = 1.0f / (e0 + e1);
        out[(size_t)b * 2 + 0] = e0 * inv;
        out[(size_t)b * 2 + 1] = e1 * inv;
    }
}

// =============================================================================
// launch
// =============================================================================
extern "C" void kernel_launch(void* const* d_in, const int* in_sizes, int n_in,
                              void* d_out, int out_size)
{
    const float* all_memory  = (const float*)d_in[0];
    const float* last_memory = (const float*)d_in[1];
    const float* Ur_w        = (const float*)d_in[2];
    const float* Wr_w        = (const float*)d_in[3];
    const float* Vre_w       = (const float*)d_in[4];
    const float* Wre_w       = (const float*)d_in[5];
    float* out = (float*)d_out;

    cudaFuncSetAttribute(score_kernel,
                         cudaFuncAttributeMaxDynamicSharedMemorySize, SMEM_TOTAL);

    whalf_kernel<<<256, 256>>>(Ur_w);
    gemm_l_kernel<<<dim3(BATCH / 32, HDIM / 128), 256>>>(last_memory, Wr_w);
    score_kernel<<<MTOT / 64, 256, SMEM_TOTAL>>>(all_memory, Vre_w);
    finish_kernel<<<BATCH, 256>>>(Wre_w, out);
}